// round 10
// baseline (speedup 1.0000x reference)
#include <cuda_runtime.h>
#include <cuda_fp16.h>
#include <cstdint>

#define BDIM   8192
#define IN_F   512
#define OUT_F  1024
#define K_TOT  1536            // [S(512) | Z(1024)], fp16 weights single-pass
#define BM 128
#define BN 128
#define BK 64                  // 64 fp16 = 128B swizzled row
#define NIT (K_TOT/BK)         // 24
#define A_BYTES (BM*BK*2)      // 16384
#define B_BYTES (BN*BK*2)      // 16384
#define SM_B_OFF (3*A_BYTES)
#define SMEM_DYN (3*A_BYTES + 3*B_BYTES + 1024)   // 99328 -> 2 CTAs/SM

__device__ __align__(16) __half g_A[(size_t)BDIM * K_TOT];   // 25.2 MB
__device__ __align__(16) __half g_B[(size_t)OUT_F * K_TOT];  // 3.1 MB

__device__ __forceinline__ uint32_t smem_u32(const void* p){
    uint32_t a;
    asm("{ .reg .u64 t; cvta.to.shared.u64 t, %1; cvt.u32.u64 %0, t; }":"=r"(a):"l"(p));
    return a;
}
__device__ __forceinline__ uint64_t gaddr(const void* p){
    uint64_t a; asm("cvta.to.global.u64 %0, %1;":"=l"(a):"l"(p)); return a;
}
__device__ __forceinline__ void cp16(uint32_t dst, uint64_t src){
    asm volatile("cp.async.cg.shared.global [%0], [%1], 16;"::"r"(dst),"l"(src));
}
__device__ __forceinline__ uint2 f4_to_h4(float4 f){
    uint2 pk;
    pk.x = (uint32_t)__half_as_ushort(__float2half_rn(f.x)) |
           ((uint32_t)__half_as_ushort(__float2half_rn(f.y))<<16);
    pk.y = (uint32_t)__half_as_ushort(__float2half_rn(f.z)) |
           ((uint32_t)__half_as_ushort(__float2half_rn(f.w))<<16);
    return pk;
}
#define LDSM4(r0,r1,r2,r3,addr) \
    asm volatile("ldmatrix.sync.aligned.m8n8.x4.shared.b16 {%0,%1,%2,%3}, [%4];" \
        : "=r"(r0),"=r"(r1),"=r"(r2),"=r"(r3) : "r"(addr))
#define MMA(d,a,b0,b1) \
    asm volatile("mma.sync.aligned.m16n8k16.row.col.f32.f16.f16.f32 " \
        "{%0,%1,%2,%3}, {%4,%5,%6,%7}, {%8,%9}, {%0,%1,%2,%3};" \
        : "+f"((d)[0]),"+f"((d)[1]),"+f"((d)[2]),"+f"((d)[3]) \
        : "r"((a)[0]),"r"((a)[1]),"r"((a)[2]),"r"((a)[3]),"r"(b0),"r"(b1))

// ---- merged prep: A=[spk|z] fp16 (binary, exact); B=[Win|Wrec] fp16 ----
#define T_SPK (BDIM*(IN_F/4))
#define T_Z   (BDIM*(OUT_F/4))
#define T_WIN ((OUT_F*IN_F)/4)
#define T_WRC ((OUT_F*OUT_F)/4)
#define T_ALL (T_SPK+T_Z+T_WIN+T_WRC)

__global__ void prep_all(const float* __restrict__ spk, const float* __restrict__ zin,
                         const float* __restrict__ win, const float* __restrict__ wrec){
    int t = blockIdx.x*blockDim.x + threadIdx.x;
    if (t < T_SPK){
        int row = t>>7, c = (t&127)<<2;
        float4 f = *reinterpret_cast<const float4*>(spk + (size_t)row*IN_F + c);
        *reinterpret_cast<uint2*>(g_A + (size_t)row*K_TOT + c) = f4_to_h4(f);
    } else if (t < T_SPK + T_Z){
        int t2 = t - T_SPK;
        int row = t2>>8, c = (t2&255)<<2;
        float4 f = *reinterpret_cast<const float4*>(zin + (size_t)row*OUT_F + c);
        *reinterpret_cast<uint2*>(g_A + (size_t)row*K_TOT + IN_F + c) = f4_to_h4(f);
    } else if (t < T_SPK + T_Z + T_WIN){
        int t2 = t - (T_SPK + T_Z);
        int o = t2>>7, c = (t2&127)<<2;
        float4 f = *reinterpret_cast<const float4*>(win + (size_t)o*IN_F + c);
        *reinterpret_cast<uint2*>(g_B + (size_t)o*K_TOT + c) = f4_to_h4(f);
    } else {
        int t2 = t - (T_SPK + T_Z + T_WIN);
        if (t2 < T_WRC){
            int o = t2>>8, c = (t2&255)<<2;
            float4 f = *reinterpret_cast<const float4*>(wrec + (size_t)o*OUT_F + c);
            *reinterpret_cast<uint2*>(g_B + (size_t)o*K_TOT + IN_F + c) = f4_to_h4(f);
        }
    }
}

// stage loader: A and B both 128 rows x 128B, XOR-8 swizzle on 16B chunks
__device__ __forceinline__ void load_stage(uint32_t sA, uint32_t sB,
                                           uint64_t ga, uint64_t gb, int tid){
    const uint64_t gs = (uint64_t)K_TOT*2;
#pragma unroll
    for (int j = 0; j < 4; j++){          // A: 128 rows * 8 chunks = 1024
        int ch = tid + j*256, r = ch>>3, c = ch&7;
        uint32_t sw = (uint32_t)(r*128 + ((c ^ (r&7))<<4));
        cp16(sA + sw, ga + (uint64_t)r*gs + c*16);
    }
#pragma unroll
    for (int j = 0; j < 4; j++){          // B: 128 rows * 8 chunks = 1024
        int ch = tid + j*256, r = ch>>3, c = ch&7;
        uint32_t sw = (uint32_t)(r*128 + ((c ^ (r&7))<<4));
        cp16(sB + sw, gb + (uint64_t)r*gs + c*16);
    }
}

__global__ void __launch_bounds__(256, 2) lsnn_gemm(
    const float* __restrict__ vin, const float* __restrict__ iin,
    const float* __restrict__ bin, float* __restrict__ out)
{
    extern __shared__ char smem_raw[];
    const uint32_t s0 = (smem_u32(smem_raw) + 1023u) & ~1023u;
    const int tid = threadIdx.x, wid = tid>>5, lane = tid&31;
    const int wm = wid & 3, wn = wid >> 2;          // 4x2 warp grid: 32m x 64n each
    const int nt = blockIdx.x & 7, mt = blockIdx.x >> 3;
    const int m0 = mt*BM, n0 = nt*BN;

    const uint64_t gA0 = gaddr(g_A) + (uint64_t)m0*K_TOT*2;
    const uint64_t gB0 = gaddr(g_B) + (uint64_t)n0*K_TOT*2;

    float acc[2][8][4];
#pragma unroll
    for (int a = 0; a < 2; a++)
#pragma unroll
        for (int b = 0; b < 8; b++)
#pragma unroll
            for (int c = 0; c < 4; c++) acc[a][b][c] = 0.0f;

    // prologue: stages 0,1
#pragma unroll
    for (int i = 0; i < 2; i++){
        load_stage(s0 + i*A_BYTES, s0 + SM_B_OFF + i*B_BYTES,
                   gA0 + (uint64_t)i*BK*2, gB0 + (uint64_t)i*BK*2, tid);
        asm volatile("cp.async.commit_group;":::"memory");
    }

    const int rA = lane & 15;
    const uint32_t hi16 = (uint32_t)((lane >> 4) << 4);
    // row offsets with swizzle bits folded in: r*128 + ((r&7)<<4); XOR-safe vs (ch<<4)
    const int arow0 = wm*32 + rA,       arow1 = arow0 + 16;
    const uint32_t roA0 = (uint32_t)(arow0*128 + ((arow0&7)<<4));
    const uint32_t roA1 = (uint32_t)(arow1*128 + ((arow1&7)<<4));
    uint32_t roB[4];
#pragma unroll
    for (int j = 0; j < 4; j++){
        int r = wn*64 + j*16 + rA;
        roB[j] = (uint32_t)(r*128 + ((r&7)<<4));
    }

    for (int i = 0; i < NIT; i++){
        asm volatile("cp.async.wait_group 1;":::"memory");
        __syncthreads();   // publish stage i; frees stage (i-1)%3

        if (i + 2 < NIT){  // prefetch overlaps the entire MMA block below
            int s = (i+2)%3;
            load_stage(s0 + s*A_BYTES, s0 + SM_B_OFF + s*B_BYTES,
                       gA0 + (uint64_t)(i+2)*BK*2, gB0 + (uint64_t)(i+2)*BK*2, tid);
        }
        asm volatile("cp.async.commit_group;":::"memory");

        // per-stage row addresses (hi16 folded via XOR-safe add/xor)
        const uint32_t aBs = s0 + (i%3)*A_BYTES;
        const uint32_t bBs = s0 + SM_B_OFF + (i%3)*B_BYTES;
        const uint32_t adA0 = (aBs + roA0) ^ hi16;
        const uint32_t adA1 = (aBs + roA1) ^ hi16;
        uint32_t adB[4];
#pragma unroll
        for (int j = 0; j < 4; j++) adB[j] = (bBs + roB[j]) ^ hi16;

        // B double-buffered across kk; A loaded at kk start (covered by 4 warps/SMSP)
        uint32_t a[2][4], b[2][4][4];
#pragma unroll
        for (int j = 0; j < 4; j++)
            LDSM4(b[0][j][0],b[0][j][1],b[0][j][2],b[0][j][3], adB[j]);   // kk=0
#pragma unroll
        for (int kk = 0; kk < 4; kk++){
            const int cur = kk & 1, nxt = cur ^ 1;
            LDSM4(a[0][0],a[0][1],a[0][2],a[0][3], adA0 ^ (kk<<5));
            LDSM4(a[1][0],a[1][1],a[1][2],a[1][3], adA1 ^ (kk<<5));
            if (kk < 3){
#pragma unroll
                for (int j = 0; j < 4; j++)
                    LDSM4(b[nxt][j][0],b[nxt][j][1],b[nxt][j][2],b[nxt][j][3],
                          adB[j] ^ ((kk+1)<<5));
            }
#pragma unroll
            for (int t = 0; t < 2; t++)
#pragma unroll
                for (int n8 = 0; n8 < 8; n8++)
                    MMA(acc[t][n8], a[t],
                        b[cur][n8>>1][n8&1], b[cur][n8>>1][(n8&1)+2]);
        }
    }

    // ---- fused LSNN epilogue (exact reference op order; rn intrinsics) ----
    const float C_VD = 0.1f;
    const float C_ID = -0.2f;
    const float C_BD = 1.25e-6f;
    const float C_BJ = 0.00225f;
    const size_t PS = (size_t)BDIM*OUT_F;

#pragma unroll
    for (int t = 0; t < 2; t++){
#pragma unroll
        for (int rr = 0; rr < 2; rr++){
            const size_t row = (size_t)(m0 + wm*32 + t*16 + rr*8 + (lane>>2));
            const float* vr = vin + row*OUT_F;
            const float* ir = iin + row*OUT_F;
            const float* br = bin + row*OUT_F;
            float* oz = out + row*OUT_F;
#pragma unroll
            for (int n8 = 0; n8 < 8; n8++){
                const int c = n0 + wn*64 + n8*8 + 2*(lane&3);
                float2 v2 = *reinterpret_cast<const float2*>(vr + c);
                float2 i2 = *reinterpret_cast<const float2*>(ir + c);
                float2 b2 = *reinterpret_cast<const float2*>(br + c);
                float vv[2] = {v2.x, v2.y}, ii[2] = {i2.x, i2.y}, bb[2] = {b2.x, b2.y};
                float zz[2], vo[2], io[2], bo[2];
#pragma unroll
                for (int e = 0; e < 2; e++){
                    float vd = __fadd_rn(vv[e], __fmul_rn(C_VD, __fadd_rn(ii[e], -vv[e])));
                    float id = __fadd_rn(ii[e], __fmul_rn(C_ID, ii[e]));
                    float bd = __fadd_rn(bb[e], __fmul_rn(C_BD, __fadd_rn(1.0f, -bb[e])));
                    float zn = (__fadd_rn(vd, -bd) > 0.0f) ? 1.0f : 0.0f;
                    zz[e] = zn;
                    vo[e] = (zn != 0.0f) ? 0.0f : vd;
                    io[e] = __fadd_rn(id, acc[t][n8][rr*2 + e]);
                    bo[e] = __fadd_rn(bd, __fmul_rn(zn, C_BJ));
                }
                *reinterpret_cast<float2*>(oz + c)        = make_float2(zz[0], zz[1]);
                *reinterpret_cast<float2*>(oz + PS + c)   = make_float2(vo[0], vo[1]);
                *reinterpret_cast<float2*>(oz + 2*PS + c) = make_float2(io[0], io[1]);
                *reinterpret_cast<float2*>(oz + 3*PS + c) = make_float2(bo[0], bo[1]);
            }
        }
    }
}

extern "C" void kernel_launch(void* const* d_in, const int* in_sizes, int n_in,
                              void* d_out, int out_size){
    const float* spikes = (const float*)d_in[0];
    const float* z      = (const float*)d_in[1];
    const float* v      = (const float*)d_in[2];
    const float* i_     = (const float*)d_in[3];
    const float* b      = (const float*)d_in[4];
    const float* win    = (const float*)d_in[5];
    const float* wrec   = (const float*)d_in[6];
    float* out = (float*)d_out;

    cudaFuncSetAttribute(lsnn_gemm, cudaFuncAttributeMaxDynamicSharedMemorySize, SMEM_DYN);

    prep_all<<<(T_ALL + 255)/256, 256>>>(spikes, z, win, wrec);
    lsnn_gemm<<<(BDIM/BM)*(OUT_F/BN), 256, SMEM_DYN>>>(v, i_, b, out);
}

// round 11
// speedup vs baseline: 1.0325x; 1.0325x over previous
#include <cuda_runtime.h>
#include <cuda_fp16.h>
#include <cstdint>

#define BDIM   8192
#define IN_F   512
#define OUT_F  1024
#define K_TOT  1536            // [S(512) | Z(1024)], fp16 weights single-pass
#define BM 128
#define BN 64
#define BK 128                 // stage = two 64-col (128B-row) swizzled sub-blocks
#define NIT (K_TOT/BK)         // 12
#define A_STAGE 32768          // 128 rows * 256B (2 halves of 16KB)
#define B_STAGE 16384          // 64 rows * 256B  (2 halves of 8KB)
#define SM_B_OFF (2*A_STAGE)
#define SMEM_DYN (2*A_STAGE + 2*B_STAGE + 1024)   // 99328

__device__ __align__(16) __half g_A[(size_t)BDIM * K_TOT];   // 25.2 MB
__device__ __align__(16) __half g_B[(size_t)OUT_F * K_TOT];  // 3.1 MB

__device__ __forceinline__ uint32_t smem_u32(const void* p){
    uint32_t a;
    asm("{ .reg .u64 t; cvta.to.shared.u64 t, %1; cvt.u32.u64 %0, t; }":"=r"(a):"l"(p));
    return a;
}
__device__ __forceinline__ uint64_t gaddr(const void* p){
    uint64_t a; asm("cvta.to.global.u64 %0, %1;":"=l"(a):"l"(p)); return a;
}
__device__ __forceinline__ void cp16(uint32_t dst, uint64_t src){
    asm volatile("cp.async.cg.shared.global [%0], [%1], 16;"::"r"(dst),"l"(src));
}
__device__ __forceinline__ uint2 f4_to_h4(float4 f){
    uint2 pk;
    pk.x = (uint32_t)__half_as_ushort(__float2half_rn(f.x)) |
           ((uint32_t)__half_as_ushort(__float2half_rn(f.y))<<16);
    pk.y = (uint32_t)__half_as_ushort(__float2half_rn(f.z)) |
           ((uint32_t)__half_as_ushort(__float2half_rn(f.w))<<16);
    return pk;
}
#define LDSM4(r0,r1,r2,r3,addr) \
    asm volatile("ldmatrix.sync.aligned.m8n8.x4.shared.b16 {%0,%1,%2,%3}, [%4];" \
        : "=r"(r0),"=r"(r1),"=r"(r2),"=r"(r3) : "r"(addr))
#define MMA(d,a,b0,b1) \
    asm volatile("mma.sync.aligned.m16n8k16.row.col.f32.f16.f16.f32 " \
        "{%0,%1,%2,%3}, {%4,%5,%6,%7}, {%8,%9}, {%0,%1,%2,%3};" \
        : "+f"((d)[0]),"+f"((d)[1]),"+f"((d)[2]),"+f"((d)[3]) \
        : "r"((a)[0]),"r"((a)[1]),"r"((a)[2]),"r"((a)[3]),"r"(b0),"r"(b1))

// ---- merged prep: A=[spk|z] fp16 (binary, exact); B=[Win|Wrec] fp16 ----
#define T_SPK (BDIM*(IN_F/4))
#define T_Z   (BDIM*(OUT_F/4))
#define T_WIN ((OUT_F*IN_F)/4)
#define T_WRC ((OUT_F*OUT_F)/4)
#define T_ALL (T_SPK+T_Z+T_WIN+T_WRC)

__global__ void prep_all(const float* __restrict__ spk, const float* __restrict__ zin,
                         const float* __restrict__ win, const float* __restrict__ wrec){
    int t = blockIdx.x*blockDim.x + threadIdx.x;
    if (t < T_SPK){
        int row = t>>7, c = (t&127)<<2;
        float4 f = *reinterpret_cast<const float4*>(spk + (size_t)row*IN_F + c);
        *reinterpret_cast<uint2*>(g_A + (size_t)row*K_TOT + c) = f4_to_h4(f);
    } else if (t < T_SPK + T_Z){
        int t2 = t - T_SPK;
        int row = t2>>8, c = (t2&255)<<2;
        float4 f = *reinterpret_cast<const float4*>(zin + (size_t)row*OUT_F + c);
        *reinterpret_cast<uint2*>(g_A + (size_t)row*K_TOT + IN_F + c) = f4_to_h4(f);
    } else if (t < T_SPK + T_Z + T_WIN){
        int t2 = t - (T_SPK + T_Z);
        int o = t2>>7, c = (t2&127)<<2;
        float4 f = *reinterpret_cast<const float4*>(win + (size_t)o*IN_F + c);
        *reinterpret_cast<uint2*>(g_B + (size_t)o*K_TOT + c) = f4_to_h4(f);
    } else {
        int t2 = t - (T_SPK + T_Z + T_WIN);
        if (t2 < T_WRC){
            int o = t2>>8, c = (t2&255)<<2;
            float4 f = *reinterpret_cast<const float4*>(wrec + (size_t)o*OUT_F + c);
            *reinterpret_cast<uint2*>(g_B + (size_t)o*K_TOT + IN_F + c) = f4_to_h4(f);
        }
    }
}

// stage loader: BK=128 as two 64-col halves, each 128B rows + XOR-8 swizzle
__device__ __forceinline__ void load_stage(uint32_t sA, uint32_t sB,
                                           uint64_t ga, uint64_t gb, int tid){
    const uint64_t gs = (uint64_t)K_TOT*2;
#pragma unroll
    for (int j = 0; j < 8; j++){          // A: 2 halves * 128 rows * 8 chunks = 2048
        int ch = tid + j*256;
        int h = ch >> 10, idx = ch & 1023, r = idx>>3, c = idx&7;
        uint32_t sw = (uint32_t)(h*16384 + r*128 + ((c ^ (r&7))<<4));
        cp16(sA + sw, ga + (uint64_t)r*gs + h*128 + c*16);
    }
#pragma unroll
    for (int j = 0; j < 4; j++){          // B: 2 halves * 64 rows * 8 chunks = 1024
        int ch = tid + j*256;
        int h = ch >> 9, idx = ch & 511, r = idx>>3, c = idx&7;
        uint32_t sw = (uint32_t)(h*8192 + r*128 + ((c ^ (r&7))<<4));
        cp16(sB + sw, gb + (uint64_t)r*gs + h*128 + c*16);
    }
}

__global__ void __launch_bounds__(256, 2) lsnn_gemm(
    const float* __restrict__ vin, const float* __restrict__ iin,
    const float* __restrict__ bin, float* __restrict__ out)
{
    extern __shared__ char smem_raw[];
    const uint32_t s0 = (smem_u32(smem_raw) + 1023u) & ~1023u;
    const int tid = threadIdx.x, wid = tid>>5, lane = tid&31;
    const int wm = wid & 3, wn = wid >> 2;          // 4x2 warp grid: 32m x 32n each
    const int nt = blockIdx.x & 15, mt = blockIdx.x >> 4;
    const int m0 = mt*BM, n0 = nt*BN;

    const uint64_t gA0 = gaddr(g_A) + (uint64_t)m0*K_TOT*2;
    const uint64_t gB0 = gaddr(g_B) + (uint64_t)n0*K_TOT*2;

    float acc[2][4][4];
#pragma unroll
    for (int a = 0; a < 2; a++)
#pragma unroll
        for (int b = 0; b < 4; b++)
#pragma unroll
            for (int c = 0; c < 4; c++) acc[a][b][c] = 0.0f;

    // prologue: stage 0
    load_stage(s0, s0 + SM_B_OFF, gA0, gB0, tid);
    asm volatile("cp.async.commit_group;":::"memory");

    const int rA = lane & 15, hi = lane >> 4;
    const int arow0 = wm*32 + rA, arow1 = wm*32 + 16 + rA;
    const int brow0 = wn*32 + rA, brow1 = wn*32 + 16 + rA;

    // precompute swizzled LDSM offsets (statically indexed -> registers)
    uint32_t offA[2][4], offB[2][4];
#pragma unroll
    for (int k4 = 0; k4 < 4; k4++){
        const int ch = k4*2 + hi;
        offA[0][k4] = (uint32_t)(arow0*128 + ((ch ^ (arow0&7))<<4));
        offA[1][k4] = (uint32_t)(arow1*128 + ((ch ^ (arow1&7))<<4));
        offB[0][k4] = (uint32_t)(brow0*128 + ((ch ^ (brow0&7))<<4));
        offB[1][k4] = (uint32_t)(brow1*128 + ((ch ^ (brow1&7))<<4));
    }

    for (int i = 0; i < NIT; i++){
        asm volatile("cp.async.wait_group 0;":::"memory");   // stage i arrived
        __syncthreads();   // publish stage i; all warps done with stage (i-1)&1

        if (i + 1 < NIT){  // prefetch next stage; overlaps entire 64-MMA block
            load_stage(s0 + ((i+1)&1)*A_STAGE, s0 + SM_B_OFF + ((i+1)&1)*B_STAGE,
                       gA0 + (uint64_t)(i+1)*BK*2, gB0 + (uint64_t)(i+1)*BK*2, tid);
        }
        asm volatile("cp.async.commit_group;":::"memory");

        if (i == NIT-3){
            // L2-prefetch epilogue state (v,i,b tile: 768 x 128B lines) so the
            // post-loop DRAM burst happens under the smem-bound mainloop.
#pragma unroll
            for (int j = 0; j < 3; j++){
                int line = tid + j*256;            // 0..767
                const float* basep = (line < 256) ? vin : (line < 512) ? iin : bin;
                int l = line & 255;                // row*2 + half
                const float* p = basep + (size_t)(m0 + (l>>1))*OUT_F + n0 + (l&1)*32;
                asm volatile("prefetch.global.L2 [%0];"::"l"(p));
            }
        }

        const uint32_t aB = s0 + (i&1)*A_STAGE;
        const uint32_t bB = s0 + SM_B_OFF + (i&1)*B_STAGE;

        // frag-double-buffered kk pipeline over 8 K=16 chunks (2 halves x 4)
        uint32_t a[2][2][4], b[2][2][4];
        LDSM4(a[0][0][0],a[0][0][1],a[0][0][2],a[0][0][3], aB + offA[0][0]);
        LDSM4(a[0][1][0],a[0][1][1],a[0][1][2],a[0][1][3], aB + offA[1][0]);
        LDSM4(b[0][0][0],b[0][0][1],b[0][0][2],b[0][0][3], bB + offB[0][0]);
        LDSM4(b[0][1][0],b[0][1][1],b[0][1][2],b[0][1][3], bB + offB[1][0]);
#pragma unroll
        for (int kk = 0; kk < 8; kk++){
            const int cur = kk & 1, nxt = cur ^ 1;
            if (kk < 7){
                const int kn = kk + 1;
                const uint32_t ha = (kn >> 2) ? 16384u : 0u;
                const uint32_t hb = (kn >> 2) ? 8192u  : 0u;
                LDSM4(a[nxt][0][0],a[nxt][0][1],a[nxt][0][2],a[nxt][0][3],
                      aB + ha + offA[0][kn&3]);
                LDSM4(a[nxt][1][0],a[nxt][1][1],a[nxt][1][2],a[nxt][1][3],
                      aB + ha + offA[1][kn&3]);
                LDSM4(b[nxt][0][0],b[nxt][0][1],b[nxt][0][2],b[nxt][0][3],
                      bB + hb + offB[0][kn&3]);
                LDSM4(b[nxt][1][0],b[nxt][1][1],b[nxt][1][2],b[nxt][1][3],
                      bB + hb + offB[1][kn&3]);
            }
#pragma unroll
            for (int t = 0; t < 2; t++)
#pragma unroll
                for (int n8 = 0; n8 < 4; n8++)
                    MMA(acc[t][n8], a[cur][t],
                        b[cur][n8>>1][n8&1], b[cur][n8>>1][(n8&1)+2]);
        }
    }

    // ---- fused LSNN epilogue (exact reference op order; rn intrinsics) ----
    const float C_VD = 0.1f;
    const float C_ID = -0.2f;
    const float C_BD = 1.25e-6f;
    const float C_BJ = 0.00225f;
    const size_t PS = (size_t)BDIM*OUT_F;

#pragma unroll
    for (int t = 0; t < 2; t++){
#pragma unroll
        for (int rr = 0; rr < 2; rr++){
            const size_t row = (size_t)(m0 + wm*32 + t*16 + rr*8 + (lane>>2));
            const float* vr = vin + row*OUT_F;
            const float* ir = iin + row*OUT_F;
            const float* br = bin + row*OUT_F;
            float* oz = out + row*OUT_F;
#pragma unroll
            for (int n8 = 0; n8 < 4; n8++){
                const int c = n0 + wn*32 + n8*8 + 2*(lane&3);
                float2 v2 = *reinterpret_cast<const float2*>(vr + c);
                float2 i2 = *reinterpret_cast<const float2*>(ir + c);
                float2 b2 = *reinterpret_cast<const float2*>(br + c);
                float vv[2] = {v2.x, v2.y}, ii[2] = {i2.x, i2.y}, bb[2] = {b2.x, b2.y};
                float zz[2], vo[2], io[2], bo[2];
#pragma unroll
                for (int e = 0; e < 2; e++){
                    float vd = __fadd_rn(vv[e], __fmul_rn(C_VD, __fadd_rn(ii[e], -vv[e])));
                    float id = __fadd_rn(ii[e], __fmul_rn(C_ID, ii[e]));
                    float bd = __fadd_rn(bb[e], __fmul_rn(C_BD, __fadd_rn(1.0f, -bb[e])));
                    float zn = (__fadd_rn(vd, -bd) > 0.0f) ? 1.0f : 0.0f;
                    zz[e] = zn;
                    vo[e] = (zn != 0.0f) ? 0.0f : vd;
                    io[e] = __fadd_rn(id, acc[t][n8][rr*2 + e]);
                    bo[e] = __fadd_rn(bd, __fmul_rn(zn, C_BJ));
                }
                *reinterpret_cast<float2*>(oz + c)        = make_float2(zz[0], zz[1]);
                *reinterpret_cast<float2*>(oz + PS + c)   = make_float2(vo[0], vo[1]);
                *reinterpret_cast<float2*>(oz + 2*PS + c) = make_float2(io[0], io[1]);
                *reinterpret_cast<float2*>(oz + 3*PS + c) = make_float2(bo[0], bo[1]);
            }
        }
    }
}

extern "C" void kernel_launch(void* const* d_in, const int* in_sizes, int n_in,
                              void* d_out, int out_size){
    const float* spikes = (const float*)d_in[0];
    const float* z      = (const float*)d_in[1];
    const float* v      = (const float*)d_in[2];
    const float* i_     = (const float*)d_in[3];
    const float* b      = (const float*)d_in[4];
    const float* win    = (const float*)d_in[5];
    const float* wrec   = (const float*)d_in[6];
    float* out = (float*)d_out;

    cudaFuncSetAttribute(lsnn_gemm, cudaFuncAttributeMaxDynamicSharedMemorySize, SMEM_DYN);

    prep_all<<<(T_ALL + 255)/256, 256>>>(spikes, z, win, wrec);
    lsnn_gemm<<<(BDIM/BM)*(OUT_F/BN), 256, SMEM_DYN>>>(v, i_, b, out);
}

// round 12
// speedup vs baseline: 1.0595x; 1.0261x over previous
#include <cuda_runtime.h>
#include <cuda_fp16.h>
#include <cstdint>

#define BDIM   8192
#define IN_F   512
#define OUT_F  1024
#define K_TOT  1536            // [S(512) | Z(1024)], fp16 weights single-pass
#define BM 128
#define BN 64
#define BK 128                 // stage = two 64-col (128B-row) swizzled sub-blocks
#define NIT (K_TOT/BK)         // 12
#define A_STAGE 32768
#define B_STAGE 16384
#define SM_B_OFF (2*A_STAGE)
#define SMEM_DYN (2*A_STAGE + 2*B_STAGE + 1024)   // 99328

__device__ __align__(16) __half g_A[(size_t)BDIM * K_TOT];   // 25.2 MB
__device__ __align__(16) __half g_B[(size_t)OUT_F * K_TOT];  // 3.1 MB

__device__ __forceinline__ uint32_t smem_u32(const void* p){
    uint32_t a;
    asm("{ .reg .u64 t; cvta.to.shared.u64 t, %1; cvt.u32.u64 %0, t; }":"=r"(a):"l"(p));
    return a;
}
__device__ __forceinline__ uint64_t gaddr(const void* p){
    uint64_t a; asm("cvta.to.global.u64 %0, %1;":"=l"(a):"l"(p)); return a;
}
__device__ __forceinline__ void cp16(uint32_t dst, uint64_t src){
    asm volatile("cp.async.cg.shared.global [%0], [%1], 16;"::"r"(dst),"l"(src));
}
__device__ __forceinline__ uint2 f4_to_h4(float4 f){
    uint2 pk;
    pk.x = (uint32_t)__half_as_ushort(__float2half_rn(f.x)) |
           ((uint32_t)__half_as_ushort(__float2half_rn(f.y))<<16);
    pk.y = (uint32_t)__half_as_ushort(__float2half_rn(f.z)) |
           ((uint32_t)__half_as_ushort(__float2half_rn(f.w))<<16);
    return pk;
}
#define LDSM4(r0,r1,r2,r3,addr) \
    asm volatile("ldmatrix.sync.aligned.m8n8.x4.shared.b16 {%0,%1,%2,%3}, [%4];" \
        : "=r"(r0),"=r"(r1),"=r"(r2),"=r"(r3) : "r"(addr))
#define MMA(d,a,b0,b1) \
    asm volatile("mma.sync.aligned.m16n8k16.row.col.f32.f16.f16.f32 " \
        "{%0,%1,%2,%3}, {%4,%5,%6,%7}, {%8,%9}, {%0,%1,%2,%3};" \
        : "+f"((d)[0]),"+f"((d)[1]),"+f"((d)[2]),"+f"((d)[3]) \
        : "r"((a)[0]),"r"((a)[1]),"r"((a)[2]),"r"((a)[3]),"r"(b0),"r"(b1))

// ---- merged prep: A=[spk|z] fp16 (binary, exact); B=[Win|Wrec] fp16 ----
#define T_SPK (BDIM*(IN_F/4))
#define T_Z   (BDIM*(OUT_F/4))
#define T_WIN ((OUT_F*IN_F)/4)
#define T_WRC ((OUT_F*OUT_F)/4)
#define T_ALL (T_SPK+T_Z+T_WIN+T_WRC)

__global__ void prep_all(const float* __restrict__ spk, const float* __restrict__ zin,
                         const float* __restrict__ win, const float* __restrict__ wrec){
    int t = blockIdx.x*blockDim.x + threadIdx.x;
    if (t < T_SPK){
        int row = t>>7, c = (t&127)<<2;
        float4 f = *reinterpret_cast<const float4*>(spk + (size_t)row*IN_F + c);
        *reinterpret_cast<uint2*>(g_A + (size_t)row*K_TOT + c) = f4_to_h4(f);
    } else if (t < T_SPK + T_Z){
        int t2 = t - T_SPK;
        int row = t2>>8, c = (t2&255)<<2;
        float4 f = *reinterpret_cast<const float4*>(zin + (size_t)row*OUT_F + c);
        *reinterpret_cast<uint2*>(g_A + (size_t)row*K_TOT + IN_F + c) = f4_to_h4(f);
    } else if (t < T_SPK + T_Z + T_WIN){
        int t2 = t - (T_SPK + T_Z);
        int o = t2>>7, c = (t2&127)<<2;
        float4 f = *reinterpret_cast<const float4*>(win + (size_t)o*IN_F + c);
        *reinterpret_cast<uint2*>(g_B + (size_t)o*K_TOT + c) = f4_to_h4(f);
    } else {
        int t2 = t - (T_SPK + T_Z + T_WIN);
        if (t2 < T_WRC){
            int o = t2>>8, c = (t2&255)<<2;
            float4 f = *reinterpret_cast<const float4*>(wrec + (size_t)o*OUT_F + c);
            *reinterpret_cast<uint2*>(g_B + (size_t)o*K_TOT + IN_F + c) = f4_to_h4(f);
        }
    }
}

__global__ void __launch_bounds__(256, 2) lsnn_gemm(
    const float* __restrict__ vin, const float* __restrict__ iin,
    const float* __restrict__ bin, float* __restrict__ out)
{
    extern __shared__ char smem_raw[];
    const uint32_t s0 = (smem_u32(smem_raw) + 1023u) & ~1023u;
    const int tid = threadIdx.x, wid = tid>>5, lane = tid&31;
    const int wm = wid & 3, wn = wid >> 2;          // 4x2 warp grid: 32m x 32n each
    const int nt = blockIdx.x & 15, mt = blockIdx.x >> 4;
    const int m0 = mt*BM, n0 = nt*BN;

    const uint64_t gA0 = gaddr(g_A) + (uint64_t)m0*K_TOT*2;
    const uint64_t gB0 = gaddr(g_B) + (uint64_t)n0*K_TOT*2;

    // ---- hoisted loader addressing (constant across iterations) ----
    uint32_t dA[8], sAo[8], dB[4], sBo[4];
#pragma unroll
    for (int j = 0; j < 8; j++){
        int ch = tid + j*256, h = ch>>10, idx = ch&1023, r = idx>>3, c = idx&7;
        dA[j]  = (uint32_t)(h*16384 + r*128 + ((c ^ (r&7))<<4));
        sAo[j] = (uint32_t)(r*(K_TOT*2) + h*128 + c*16);
    }
#pragma unroll
    for (int j = 0; j < 4; j++){
        int ch = tid + j*256, h = ch>>9, idx = ch&511, r = idx>>3, c = idx&7;
        dB[j]  = (uint32_t)(h*8192 + r*128 + ((c ^ (r&7))<<4));
        sBo[j] = (uint32_t)(r*(K_TOT*2) + h*128 + c*16);
    }
#define LOAD_STAGE(par, it) do{ \
        const uint32_t _sa = s0 + (par)*A_STAGE; \
        const uint32_t _sb = s0 + SM_B_OFF + (par)*B_STAGE; \
        const uint64_t _ga = gA0 + (uint32_t)((it)*(BK*2)); \
        const uint64_t _gb = gB0 + (uint32_t)((it)*(BK*2)); \
        _Pragma("unroll") \
        for (int _j = 0; _j < 8; _j++) cp16(_sa + dA[_j], _ga + sAo[_j]); \
        _Pragma("unroll") \
        for (int _j = 0; _j < 4; _j++) cp16(_sb + dB[_j], _gb + sBo[_j]); \
    }while(0)

    float acc[2][4][4];
#pragma unroll
    for (int a = 0; a < 2; a++)
#pragma unroll
        for (int b = 0; b < 4; b++)
#pragma unroll
            for (int c = 0; c < 4; c++) acc[a][b][c] = 0.0f;

    // prologue: stage 0
    LOAD_STAGE(0, 0);
    asm volatile("cp.async.commit_group;":::"memory");

    const int rA = lane & 15, hi = lane >> 4;
    const int arow0 = wm*32 + rA, arow1 = wm*32 + 16 + rA;
    const int brow0 = wn*32 + rA, brow1 = wn*32 + 16 + rA;

    uint32_t offA[2][4], offB[2][4];
#pragma unroll
    for (int k4 = 0; k4 < 4; k4++){
        const int ch = k4*2 + hi;
        offA[0][k4] = (uint32_t)(arow0*128 + ((ch ^ (arow0&7))<<4));
        offA[1][k4] = (uint32_t)(arow1*128 + ((ch ^ (arow1&7))<<4));
        offB[0][k4] = (uint32_t)(brow0*128 + ((ch ^ (brow0&7))<<4));
        offB[1][k4] = (uint32_t)(brow1*128 + ((ch ^ (brow1&7))<<4));
    }

    for (int i = 0; i < NIT; i++){
        asm volatile("cp.async.wait_group 0;":::"memory");   // stage i arrived
        __syncthreads();   // publish stage i; all warps done with stage (i-1)&1

        if (i + 1 < NIT)   // prefetch next stage; overlaps entire 64-MMA block
            LOAD_STAGE((i+1)&1, i+1);
        asm volatile("cp.async.commit_group;":::"memory");

        const uint32_t aB = s0 + (i&1)*A_STAGE;
        const uint32_t bB = s0 + SM_B_OFF + (i&1)*B_STAGE;

        // frag-double-buffered kk pipeline over 8 K=16 chunks (2 halves x 4)
        uint32_t a[2][2][4], b[2][2][4];
        LDSM4(a[0][0][0],a[0][0][1],a[0][0][2],a[0][0][3], aB + offA[0][0]);
        LDSM4(a[0][1][0],a[0][1][1],a[0][1][2],a[0][1][3], aB + offA[1][0]);
        LDSM4(b[0][0][0],b[0][0][1],b[0][0][2],b[0][0][3], bB + offB[0][0]);
        LDSM4(b[0][1][0],b[0][1][1],b[0][1][2],b[0][1][3], bB + offB[1][0]);
#pragma unroll
        for (int kk = 0; kk < 8; kk++){
            const int cur = kk & 1, nxt = cur ^ 1;
            if (kk < 7){
                const int kn = kk + 1;
                const uint32_t ha = (kn >> 2) ? 16384u : 0u;
                const uint32_t hb = (kn >> 2) ? 8192u  : 0u;
                LDSM4(a[nxt][0][0],a[nxt][0][1],a[nxt][0][2],a[nxt][0][3],
                      aB + ha + offA[0][kn&3]);
                LDSM4(a[nxt][1][0],a[nxt][1][1],a[nxt][1][2],a[nxt][1][3],
                      aB + ha + offA[1][kn&3]);
                LDSM4(b[nxt][0][0],b[nxt][0][1],b[nxt][0][2],b[nxt][0][3],
                      bB + hb + offB[0][kn&3]);
                LDSM4(b[nxt][1][0],b[nxt][1][1],b[nxt][1][2],b[nxt][1][3],
                      bB + hb + offB[1][kn&3]);
            }
#pragma unroll
            for (int t = 0; t < 2; t++)
#pragma unroll
                for (int n8 = 0; n8 < 4; n8++)
                    MMA(acc[t][n8], a[cur][t],
                        b[cur][n8>>1][n8&1], b[cur][n8>>1][(n8&1)+2]);
        }
    }

    // ---- fused LSNN epilogue (exact reference op order; 32-bit addressing) ----
    const float C_VD = 0.1f;
    const float C_ID = -0.2f;
    const float C_BD = 1.25e-6f;
    const float C_BJ = 0.00225f;
    const uint32_t PSB = (uint32_t)(BDIM*OUT_F*4);   // plane stride in bytes

    const uint32_t colb = (uint32_t)((n0 + wn*32 + 2*(lane&3)) * 4);
#pragma unroll
    for (int t = 0; t < 2; t++){
#pragma unroll
        for (int rr = 0; rr < 2; rr++){
            const uint32_t ro = ((uint32_t)(m0 + wm*32 + t*16 + rr*8 + (lane>>2)) << 12)
                                + colb;               // row*4096 + col*4 bytes
            const char* vb = (const char*)vin + ro;
            const char* ib = (const char*)iin + ro;
            const char* bb_ = (const char*)bin + ro;
            char* ob = (char*)out + ro;
#pragma unroll
            for (int n8 = 0; n8 < 4; n8++){
                const uint32_t co = (uint32_t)(n8*32);   // 8 floats per n8 step
                float2 v2 = *reinterpret_cast<const float2*>(vb + co);
                float2 i2 = *reinterpret_cast<const float2*>(ib + co);
                float2 b2 = *reinterpret_cast<const float2*>(bb_ + co);
                float vv[2] = {v2.x, v2.y}, ii[2] = {i2.x, i2.y}, bbv[2] = {b2.x, b2.y};
                float zz[2], vo[2], io[2], bo[2];
#pragma unroll
                for (int e = 0; e < 2; e++){
                    float vd = __fadd_rn(vv[e], __fmul_rn(C_VD, __fadd_rn(ii[e], -vv[e])));
                    float id = __fadd_rn(ii[e], __fmul_rn(C_ID, ii[e]));
                    float bd = __fadd_rn(bbv[e], __fmul_rn(C_BD, __fadd_rn(1.0f, -bbv[e])));
                    float zn = (__fadd_rn(vd, -bd) > 0.0f) ? 1.0f : 0.0f;
                    zz[e] = zn;
                    vo[e] = (zn != 0.0f) ? 0.0f : vd;
                    io[e] = __fadd_rn(id, acc[t][n8][rr*2 + e]);
                    bo[e] = __fadd_rn(bd, __fmul_rn(zn, C_BJ));
                }
                *reinterpret_cast<float2*>(ob + co)           = make_float2(zz[0], zz[1]);
                *reinterpret_cast<float2*>(ob + PSB + co)     = make_float2(vo[0], vo[1]);
                *reinterpret_cast<float2*>(ob + 2u*PSB + co)  = make_float2(io[0], io[1]);
                *reinterpret_cast<float2*>(ob + 3u*PSB + co)  = make_float2(bo[0], bo[1]);
            }
        }
    }
}

extern "C" void kernel_launch(void* const* d_in, const int* in_sizes, int n_in,
                              void* d_out, int out_size){
    const float* spikes = (const float*)d_in[0];
    const float* z      = (const float*)d_in[1];
    const float* v      = (const float*)d_in[2];
    const float* i_     = (const float*)d_in[3];
    const float* b      = (const float*)d_in[4];
    const float* win    = (const float*)d_in[5];
    const float* wrec   = (const float*)d_in[6];
    float* out = (float*)d_out;

    cudaFuncSetAttribute(lsnn_gemm, cudaFuncAttributeMaxDynamicSharedMemorySize, SMEM_DYN);

    prep_all<<<(T_ALL + 255)/256, 256>>>(spikes, z, win, wrec);
    lsnn_gemm<<<(BDIM/BM)*(OUT_F/BN), 256, SMEM_DYN>>>(v, i_, b, out);
}

// round 13
// speedup vs baseline: 1.0850x; 1.0241x over previous
#include <cuda_runtime.h>
#include <cuda_fp16.h>
#include <cstdint>

#define BDIM   8192
#define IN_F   512
#define OUT_F  1024
#define K_TOT  1536            // [S(512) | Z(1024)], fp16 weights single-pass
#define BM 128
#define BN 64
#define BK 128                 // stage = two 64-col (128B-row) swizzled sub-blocks
#define NIT (K_TOT/BK)         // 12
#define A_STAGE 32768
#define B_STAGE 16384
#define SM_B_OFF (2*A_STAGE)
#define SMEM_DYN (2*A_STAGE + 2*B_STAGE + 1024)   // 99328
#define NTILES 1024            // (8192/128)*(1024/64)
#define GRID   296             // 2 CTAs x 148 SMs, persistent

__device__ __align__(16) __half g_A[(size_t)BDIM * K_TOT];   // 25.2 MB
__device__ __align__(16) __half g_B[(size_t)OUT_F * K_TOT];  // 3.1 MB

__device__ __forceinline__ uint32_t smem_u32(const void* p){
    uint32_t a;
    asm("{ .reg .u64 t; cvta.to.shared.u64 t, %1; cvt.u32.u64 %0, t; }":"=r"(a):"l"(p));
    return a;
}
__device__ __forceinline__ uint64_t gaddr(const void* p){
    uint64_t a; asm("cvta.to.global.u64 %0, %1;":"=l"(a):"l"(p)); return a;
}
__device__ __forceinline__ void cp16(uint32_t dst, uint64_t src){
    asm volatile("cp.async.cg.shared.global [%0], [%1], 16;"::"r"(dst),"l"(src));
}
__device__ __forceinline__ uint2 f4_to_h4(float4 f){
    uint2 pk;
    pk.x = (uint32_t)__half_as_ushort(__float2half_rn(f.x)) |
           ((uint32_t)__half_as_ushort(__float2half_rn(f.y))<<16);
    pk.y = (uint32_t)__half_as_ushort(__float2half_rn(f.z)) |
           ((uint32_t)__half_as_ushort(__float2half_rn(f.w))<<16);
    return pk;
}
#define LDSM4(r0,r1,r2,r3,addr) \
    asm volatile("ldmatrix.sync.aligned.m8n8.x4.shared.b16 {%0,%1,%2,%3}, [%4];" \
        : "=r"(r0),"=r"(r1),"=r"(r2),"=r"(r3) : "r"(addr))
#define MMA(d,a,b0,b1) \
    asm volatile("mma.sync.aligned.m16n8k16.row.col.f32.f16.f16.f32 " \
        "{%0,%1,%2,%3}, {%4,%5,%6,%7}, {%8,%9}, {%0,%1,%2,%3};" \
        : "+f"((d)[0]),"+f"((d)[1]),"+f"((d)[2]),"+f"((d)[3]) \
        : "r"((a)[0]),"r"((a)[1]),"r"((a)[2]),"r"((a)[3]),"r"(b0),"r"(b1))

// ---- merged prep: A=[spk|z] fp16 (binary, exact); B=[Win|Wrec] fp16 ----
#define T_SPK (BDIM*(IN_F/4))
#define T_Z   (BDIM*(OUT_F/4))
#define T_WIN ((OUT_F*IN_F)/4)
#define T_WRC ((OUT_F*OUT_F)/4)
#define T_ALL (T_SPK+T_Z+T_WIN+T_WRC)

__global__ void prep_all(const float* __restrict__ spk, const float* __restrict__ zin,
                         const float* __restrict__ win, const float* __restrict__ wrec){
    int t = blockIdx.x*blockDim.x + threadIdx.x;
    if (t < T_SPK){
        int row = t>>7, c = (t&127)<<2;
        float4 f = *reinterpret_cast<const float4*>(spk + (size_t)row*IN_F + c);
        *reinterpret_cast<uint2*>(g_A + (size_t)row*K_TOT + c) = f4_to_h4(f);
    } else if (t < T_SPK + T_Z){
        int t2 = t - T_SPK;
        int row = t2>>8, c = (t2&255)<<2;
        float4 f = *reinterpret_cast<const float4*>(zin + (size_t)row*OUT_F + c);
        *reinterpret_cast<uint2*>(g_A + (size_t)row*K_TOT + IN_F + c) = f4_to_h4(f);
    } else if (t < T_SPK + T_Z + T_WIN){
        int t2 = t - (T_SPK + T_Z);
        int o = t2>>7, c = (t2&127)<<2;
        float4 f = *reinterpret_cast<const float4*>(win + (size_t)o*IN_F + c);
        *reinterpret_cast<uint2*>(g_B + (size_t)o*K_TOT + c) = f4_to_h4(f);
    } else {
        int t2 = t - (T_SPK + T_Z + T_WIN);
        if (t2 < T_WRC){
            int o = t2>>8, c = (t2&255)<<2;
            float4 f = *reinterpret_cast<const float4*>(wrec + (size_t)o*OUT_F + c);
            *reinterpret_cast<uint2*>(g_B + (size_t)o*K_TOT + IN_F + c) = f4_to_h4(f);
        }
    }
}

__global__ void __launch_bounds__(256, 2) lsnn_gemm(
    const float* __restrict__ vin, const float* __restrict__ iin,
    const float* __restrict__ bin, float* __restrict__ out)
{
    extern __shared__ char smem_raw[];
    const uint32_t s0 = (smem_u32(smem_raw) + 1023u) & ~1023u;
    const int tid = threadIdx.x, wid = tid>>5, lane = tid&31;
    const int wm = wid & 3, wn = wid >> 2;          // 4x2 warp grid: 32m x 32n each

    // ---- hoisted loader addressing (constant across iterations) ----
    uint32_t dA[8], sAo[8], dB[4], sBo[4];
#pragma unroll
    for (int j = 0; j < 8; j++){
        int ch = tid + j*256, h = ch>>10, idx = ch&1023, r = idx>>3, c = idx&7;
        dA[j]  = (uint32_t)(h*16384 + r*128 + ((c ^ (r&7))<<4));
        sAo[j] = (uint32_t)(r*(K_TOT*2) + h*128 + c*16);
    }
#pragma unroll
    for (int j = 0; j < 4; j++){
        int ch = tid + j*256, h = ch>>9, idx = ch&511, r = idx>>3, c = idx&7;
        dB[j]  = (uint32_t)(h*8192 + r*128 + ((c ^ (r&7))<<4));
        sBo[j] = (uint32_t)(r*(K_TOT*2) + h*128 + c*16);
    }
#define LOAD_STAGE(par, ga, gb, it) do{ \
        const uint32_t _sa = s0 + (par)*A_STAGE; \
        const uint32_t _sb = s0 + SM_B_OFF + (par)*B_STAGE; \
        const uint64_t _ga = (ga) + (uint32_t)((it)*(BK*2)); \
        const uint64_t _gb = (gb) + (uint32_t)((it)*(BK*2)); \
        _Pragma("unroll") \
        for (int _j = 0; _j < 8; _j++) cp16(_sa + dA[_j], _ga + sAo[_j]); \
        _Pragma("unroll") \
        for (int _j = 0; _j < 4; _j++) cp16(_sb + dB[_j], _gb + sBo[_j]); \
    }while(0)

    const int rA = lane & 15, hi = lane >> 4;
    const int arow0 = wm*32 + rA, arow1 = wm*32 + 16 + rA;
    const int brow0 = wn*32 + rA, brow1 = wn*32 + 16 + rA;
    uint32_t offA[2][4], offB[2][4];
#pragma unroll
    for (int k4 = 0; k4 < 4; k4++){
        const int ch = k4*2 + hi;
        offA[0][k4] = (uint32_t)(arow0*128 + ((ch ^ (arow0&7))<<4));
        offA[1][k4] = (uint32_t)(arow1*128 + ((ch ^ (arow1&7))<<4));
        offB[0][k4] = (uint32_t)(brow0*128 + ((ch ^ (brow0&7))<<4));
        offB[1][k4] = (uint32_t)(brow1*128 + ((ch ^ (brow1&7))<<4));
    }

    const float C_VD = 0.1f;
    const float C_ID = -0.2f;
    const float C_BD = 1.25e-6f;
    const float C_BJ = 0.00225f;
    const uint32_t PSB = (uint32_t)(BDIM*OUT_F*4);
    const uint32_t colb0 = (uint32_t)((wn*32 + 2*(lane&3)) * 4);
    const uint64_t gAbase = gaddr(g_A), gBbase = gaddr(g_B);

    // ---- persistent tile loop ----
    const int tile0 = blockIdx.x;
    uint64_t gAc = gAbase + (uint64_t)((tile0>>4)*BM)*(K_TOT*2);
    uint64_t gBc = gBbase + (uint64_t)((tile0&15)*BN)*(K_TOT*2);
    LOAD_STAGE(0, gAc, gBc, 0);                     // prologue: first tile stage 0
    asm volatile("cp.async.commit_group;":::"memory");

    for (int t = tile0; t < NTILES; t += GRID){
        const int m0 = (t>>4)*BM, n0 = (t&15)*BN;
        const int tn = t + GRID;
        const bool hn = (tn < NTILES);
        const uint64_t gAn = hn ? gAbase + (uint64_t)((tn>>4)*BM)*(K_TOT*2) : 0;
        const uint64_t gBn = hn ? gBbase + (uint64_t)((tn&15)*BN)*(K_TOT*2) : 0;

        float acc[2][4][4];
#pragma unroll
        for (int a = 0; a < 2; a++)
#pragma unroll
            for (int b = 0; b < 4; b++)
#pragma unroll
                for (int c = 0; c < 4; c++) acc[a][b][c] = 0.0f;

        for (int i = 0; i < NIT; i++){
            asm volatile("cp.async.wait_group 0;":::"memory");  // stage i arrived
            __syncthreads();   // publish stage i; all warps done with stage (i-1)&1

            if (i + 1 < NIT)      LOAD_STAGE((i+1)&1, gAc, gBc, i+1);
            else if (hn)          LOAD_STAGE(0, gAn, gBn, 0);   // next tile's stage 0
            asm volatile("cp.async.commit_group;":::"memory");

            const uint32_t aB = s0 + (i&1)*A_STAGE;
            const uint32_t bB = s0 + SM_B_OFF + (i&1)*B_STAGE;

            uint32_t a[2][2][4], b[2][2][4];
            LDSM4(a[0][0][0],a[0][0][1],a[0][0][2],a[0][0][3], aB + offA[0][0]);
            LDSM4(a[0][1][0],a[0][1][1],a[0][1][2],a[0][1][3], aB + offA[1][0]);
            LDSM4(b[0][0][0],b[0][0][1],b[0][0][2],b[0][0][3], bB + offB[0][0]);
            LDSM4(b[0][1][0],b[0][1][1],b[0][1][2],b[0][1][3], bB + offB[1][0]);
#pragma unroll
            for (int kk = 0; kk < 8; kk++){
                const int cur = kk & 1, nxt = cur ^ 1;
                if (kk < 7){
                    const int kn = kk + 1;
                    const uint32_t ha = (kn >> 2) ? 16384u : 0u;
                    const uint32_t hb = (kn >> 2) ? 8192u  : 0u;
                    LDSM4(a[nxt][0][0],a[nxt][0][1],a[nxt][0][2],a[nxt][0][3],
                          aB + ha + offA[0][kn&3]);
                    LDSM4(a[nxt][1][0],a[nxt][1][1],a[nxt][1][2],a[nxt][1][3],
                          aB + ha + offA[1][kn&3]);
                    LDSM4(b[nxt][0][0],b[nxt][0][1],b[nxt][0][2],b[nxt][0][3],
                          bB + hb + offB[0][kn&3]);
                    LDSM4(b[nxt][1][0],b[nxt][1][1],b[nxt][1][2],b[nxt][1][3],
                          bB + hb + offB[1][kn&3]);
                }
#pragma unroll
                for (int tt = 0; tt < 2; tt++)
#pragma unroll
                    for (int n8 = 0; n8 < 4; n8++)
                        MMA(acc[tt][n8], a[cur][tt],
                            b[cur][n8>>1][n8&1], b[cur][n8>>1][(n8&1)+2]);
            }
        }

        // ---- fused epilogue (overlaps next tile's stage-0 cp.async in flight) ----
        const uint32_t colb = colb0 + (uint32_t)(n0*4);
#pragma unroll
        for (int tt = 0; tt < 2; tt++){
#pragma unroll
            for (int rr = 0; rr < 2; rr++){
                const uint32_t ro = ((uint32_t)(m0 + wm*32 + tt*16 + rr*8 + (lane>>2)) << 12)
                                    + colb;
                const char* vb  = (const char*)vin + ro;
                const char* ib  = (const char*)iin + ro;
                const char* bb_ = (const char*)bin + ro;
                char* ob = (char*)out + ro;
#pragma unroll
                for (int n8 = 0; n8 < 4; n8++){
                    const uint32_t co = (uint32_t)(n8*32);
                    float2 v2 = *reinterpret_cast<const float2*>(vb + co);
                    float2 i2 = *reinterpret_cast<const float2*>(ib + co);
                    float2 b2 = *reinterpret_cast<const float2*>(bb_ + co);
                    float vv[2] = {v2.x, v2.y}, ii[2] = {i2.x, i2.y}, bbv[2] = {b2.x, b2.y};
                    float zz[2], vo[2], io[2], bo[2];
#pragma unroll
                    for (int e = 0; e < 2; e++){
                        float vd = __fadd_rn(vv[e], __fmul_rn(C_VD, __fadd_rn(ii[e], -vv[e])));
                        float id = __fadd_rn(ii[e], __fmul_rn(C_ID, ii[e]));
                        float bd = __fadd_rn(bbv[e], __fmul_rn(C_BD, __fadd_rn(1.0f, -bbv[e])));
                        float zn = (__fadd_rn(vd, -bd) > 0.0f) ? 1.0f : 0.0f;
                        zz[e] = zn;
                        vo[e] = (zn != 0.0f) ? 0.0f : vd;
                        io[e] = __fadd_rn(id, acc[tt][n8][rr*2 + e]);
                        bo[e] = __fadd_rn(bd, __fmul_rn(zn, C_BJ));
                    }
                    *reinterpret_cast<float2*>(ob + co)           = make_float2(zz[0], zz[1]);
                    *reinterpret_cast<float2*>(ob + PSB + co)     = make_float2(vo[0], vo[1]);
                    *reinterpret_cast<float2*>(ob + 2u*PSB + co)  = make_float2(io[0], io[1]);
                    *reinterpret_cast<float2*>(ob + 3u*PSB + co)  = make_float2(bo[0], bo[1]);
                }
            }
        }

        gAc = gAn; gBc = gBn;
    }
}

extern "C" void kernel_launch(void* const* d_in, const int* in_sizes, int n_in,
                              void* d_out, int out_size){
    const float* spikes = (const float*)d_in[0];
    const float* z      = (const float*)d_in[1];
    const float* v      = (const float*)d_in[2];
    const float* i_     = (const float*)d_in[3];
    const float* b      = (const float*)d_in[4];
    const float* win    = (const float*)d_in[5];
    const float* wrec   = (const float*)d_in[6];
    float* out = (float*)d_out;

    cudaFuncSetAttribute(lsnn_gemm, cudaFuncAttributeMaxDynamicSharedMemorySize, SMEM_DYN);

    prep_all<<<(T_ALL + 255)/256, 256>>>(spikes, z, win, wrec);
    lsnn_gemm<<<GRID, 256, SMEM_DYN>>>(v, i_, b, out);
}